// round 11
// baseline (speedup 1.0000x reference)
#include <cuda_runtime.h>
#include <cuda_fp16.h>

// RC backward-Euler scan. v10: FUSED single kernel.
//  - Each CTA (64 threads) computes coefficients for its 66 columns
//    (64 output chunks + 2 warm-up) into SMEM, then scans from SMEM.
//    Coefficients never touch L2/DRAM -> eliminates the 32 MB round-trip
//    plus the 96 MB scan re-read that bounded v4..v9.
//  - S=128 steps/chunk, warm-up = 2 chunks (256 steps), same math as v9.
//  - smem [step][col(+pad via NC=66)] -> phase-B reads conflict-free.
//  - block-0 negative columns: clamped input loads + exact carry reset.

#define DT_S   1800.0f
#define GA     31.388f
#define S2     128
#define PWARM  2
#define TPB    64
#define NC     (TPB + PWARM)          // 66 columns per CTA
#define NITER  ((NC * S2 / 4) / TPB)  // 33 quads per thread in phase A
#define SMEMB  (S2 * NC * 8)          // 67584 B: float b + packed half2 (h,g)
#define NMAX   (1 << 22)

struct DCst {
    float iRie, iRea, invCin, invCen;
    float M11, nM12, nM21;
    float kD, kE, k0a, k1a;
    float gam, del, c_h, c_g1, dtCen;
};

__device__ __forceinline__ DCst make_consts(float R_ie, float R_ea,
                                            float C_in, float C_en)
{
    DCst c;
    c.iRie   = 1.0f / R_ie;
    c.iRea   = 1.0f / R_ea;
    c.invCin = 1.0f / C_in;
    c.invCen = 1.0f / C_en;
    c.M11  = 1.0f + DT_S * (c.iRea + c.iRie) * c.invCen;
    c.nM12 = DT_S * c.iRie * c.invCen;
    c.nM21 = DT_S * c.iRie * c.invCin;
    c.kD   = c.M11  / c.nM12;
    c.kE   = c.nM21 / c.nM12;
    c.k0a  = 1.0f / c.M11;
    c.k1a  = c.nM21 / c.M11;
    float alpha = 1.0f + DT_S * c.iRie * c.invCin;   // M22 = alpha + beta*u
    float beta  = DT_S * c.invCin;
    c.gam  = c.M11 * alpha - c.nM12 * c.nM21;        // det = gam + del*u
    c.del  = c.M11 * beta;
    c.c_h  = c.nM12 * DT_S * c.invCin;
    c.c_g1 = c.M11  * DT_S * c.invCin;
    c.dtCen = DT_S * c.invCen;
    return c;
}

__device__ __forceinline__ float frcp_approx(float x) {
    float r;
    asm("rcp.approx.f32 %0, %1;" : "=f"(r) : "f"(x));
    return r;
}

// --------------------------------------------------------- fused kernel
__global__ void __launch_bounds__(TPB)
fused_kernel(const float* __restrict__ To,  const float* __restrict__ Irr,
             const float* __restrict__ Qint, const float* __restrict__ Qah,
             const float* __restrict__ Ria,
             const float* pR_ie, const float* pR_ea,
             const float* pC_in, const float* pC_en,
             const float* pA_si, const float* pA_se,
             const float* pA_ii, const float* pA_ie,
             const float* pTin0,
             float* __restrict__ out)
{
    extern __shared__ char dyn[];
    float*    sbuf = (float*)dyn;                       // [S2][NC] b
    unsigned* hbuf = (unsigned*)(dyn + S2 * NC * 4);    // [S2][NC] (h,g) half2

    const DCst c = make_consts(__ldg(pR_ie), __ldg(pR_ea), __ldg(pC_in), __ldg(pC_en));
    float a_si = __ldg(pA_si), a_se = __ldg(pA_se);
    float a_ii = __ldg(pA_ii), a_ie = __ldg(pA_ie);
    float Tin0 = __ldg(pTin0);

    const int tid  = threadIdx.x;
    const int base = (blockIdx.x * TPB - PWARM) * S2;   // global t of local 0 (may be <0)

    // ---------------- phase A: inputs -> coefficients -> smem ----------------
    #pragma unroll 1
    for (int m = 0; m < NITER; ++m) {
        int i  = 4 * (tid + TPB * m);      // local element index (quad-aligned)
        int tg = base + i; if (tg < 0) tg = 0;   // block 0 dummy cols: clamp

        float4 to4 = *(const float4*)(To  + tg);
        float4 ir4 = *(const float4*)(Irr + tg);
        float4 qi4 = *(const float4*)(Qint + tg);
        float4 qa4 = *(const float4*)(Qah + tg);
        float4 ra4 = *(const float4*)(Ria + tg);
        const float* to = (const float*)&to4;
        const float* ir = (const float*)&ir4;
        const float* qi = (const float*)&qi4;
        const float* qa = (const float*)&qa4;
        const float* ra = (const float*)&ra4;

        // batched reciprocal of P_i = gam*Ria_c + del (1 MUFU per 4 steps)
        float Rc[4], P[4], ipv[4];
        #pragma unroll
        for (int r = 0; r < 4; ++r) {
            Rc[r] = fmaxf(ra[r], 1e-4f);
            P[r]  = fmaf(c.gam, Rc[r], c.del);
        }
        float p01 = P[0] * P[1], p23 = P[2] * P[3];
        float ipa = frcp_approx(p01 * p23);
        float i01 = ipa * p23, i23 = ipa * p01;
        ipv[0] = i01 * P[1]; ipv[1] = i01 * P[0];
        ipv[2] = i23 * P[3]; ipv[3] = i23 * P[2];
        #pragma unroll
        for (int r = 0; r < 4; ++r)        // one Newton polish
            ipv[r] = ipv[r] * fmaf(-P[r], ipv[r], 2.0f);

        int L = i >> 7;          // local column
        int k = i & 127;         // step within column
        #pragma unroll
        for (int r = 0; r < 4; ++r) {
            float ip  = ipv[r];
            float rp  = Rc[r] * ip;                 // invdet
            float Qs  = GA * fminf(fmaxf(ir[r], 0.0f), 2000.0f);
            float qh  = fmaxf(qa[r], 0.0f);
            float b   = c.nM12 * rp;
            float a   = fmaf(c.k1a, b, c.k0a);
            float s0  = c.dtCen * fmaf(to[r], c.iRea,
                                 fmaf(a_se, Qs, a_ie * qi[r]));
            float s1  = fmaf(a_si, Qs, fmaf(a_ii, qi[r], qh));
            float T1  = ip * fmaf(Rc[r], s1, to[r]);
            float h   = fmaf(c.c_h, T1, a * s0);
            float g   = fmaf(c.c_g1, T1, c.nM21 * (rp * s0));
            __half2 pk = __floats2half2_rn(h, g);
            sbuf[(k + r) * NC + L] = b;
            hbuf[(k + r) * NC + L] = *reinterpret_cast<unsigned*>(&pk);
        }
    }
    __syncthreads();

    // ---------------- phase B: scan from smem ----------------
    float kD = c.kD, kE = c.kE, k0a = c.k0a, k1a = c.k1a;
    float Te = Tin0, Tin = Tin0;
    int gcolW = blockIdx.x * TPB + tid - PWARM;   // global col of seg 0

    // warm-up segments (no output)
    #pragma unroll 1
    for (int seg = 0; seg < PWARM; ++seg) {
        const float*    sp = sbuf + (tid + seg);
        const unsigned* hp = hbuf + (tid + seg);
        #pragma unroll 8
        for (int k = 0; k < S2; ++k) {
            float b = sp[k * NC];
            unsigned u = hp[k * NC];
            float2 hg = __half22float2(*reinterpret_cast<const __half2*>(&u));
            float a  = fmaf(k1a, b, k0a);
            float dd = kD * b;
            float ee = kE * b;
            float p  = fmaf(b,  Tin, hg.x);
            float q  = fmaf(ee, Te,  hg.y);
            float Te_n  = fmaf(a,  Te,  p);
            float Tin_n = fmaf(dd, Tin, q);
            Tin_n = fminf(fmaxf(Tin_n, 5.0f), 45.0f);
            Te = Te_n; Tin = Tin_n;
        }
        // dummy (clamped) column processed: restore exact initial carry
        if (gcolW + seg < 0) { Te = Tin0; Tin = Tin0; }
    }

    // output segment
    {
        const float*    sp = sbuf + (tid + PWARM);
        const unsigned* hp = hbuf + (tid + PWARM);
        float* outp = out + (blockIdx.x * TPB + tid) * S2;
        #pragma unroll 4
        for (int k = 0; k < S2; k += 4) {
            float4 v; float* vv = (float*)&v;
            #pragma unroll
            for (int e = 0; e < 4; ++e) {
                float b = sp[(k + e) * NC];
                unsigned u = hp[(k + e) * NC];
                float2 hg = __half22float2(*reinterpret_cast<const __half2*>(&u));
                float a  = fmaf(k1a, b, k0a);
                float dd = kD * b;
                float ee = kE * b;
                float p  = fmaf(b,  Tin, hg.x);
                float q  = fmaf(ee, Te,  hg.y);
                float Te_n  = fmaf(a,  Te,  p);
                float Tin_n = fmaf(dd, Tin, q);
                Tin_n = fminf(fmaxf(Tin_n, 5.0f), 45.0f);
                Te = Te_n; Tin = Tin_n;
                vv[e] = Tin;
            }
            __stcs((float4*)(outp + k), v);
        }
    }
}

// ------------------------------------------- exact fallback (ragged n only)
__global__ void seq_kernel(const float* __restrict__ To, const float* __restrict__ Irr,
                           const float* __restrict__ Qint, const float* __restrict__ Qah,
                           const float* __restrict__ Ria,
                           const float* pR_ie, const float* pR_ea,
                           const float* pC_in, const float* pC_en,
                           const float* pA_si, const float* pA_se,
                           const float* pA_ii, const float* pA_ie,
                           const float* pTin0,
                           float* __restrict__ out, int n)
{
    float iRie = 1.0f / *pR_ie, iRea = 1.0f / *pR_ea;
    float invCin = 1.0f / *pC_in, invCen = 1.0f / *pC_en;
    float a_si = *pA_si, a_se = *pA_se, a_ii = *pA_ii, a_ie = *pA_ie;
    float M11  = 1.0f + DT_S * (iRea + iRie) * invCen;
    float nM12 = DT_S * iRie * invCen;
    float nM21 = DT_S * iRie * invCin;
    float Te = *pTin0, Tin = *pTin0;
    for (int t = 0; t < n; ++t) {
        float Ria_c = fmaxf(Ria[t], 1e-4f);
        float u     = 1.0f / Ria_c;
        float Qsol  = GA * fminf(fmaxf(Irr[t], 0.0f), 2000.0f);
        float qah   = fmaxf(Qah[t], 0.0f);
        float M22 = 1.0f + DT_S * (u + iRie) * invCin;
        float det = M11 * M22 - nM12 * nM21;
        float invdet = 1.0f / det;
        float b0 = To[t] * iRea * invCen + (a_se * Qsol + a_ie * Qint[t]) * invCen;
        float b1 = (To[t] * u + a_si * Qsol + a_ii * Qint[t] + qah) * invCin;
        float r0 = Te + DT_S * b0;
        float r1 = Tin + DT_S * b1;
        float Te_n  = (M22 * r0 + nM12 * r1) * invdet;
        float Tin_n = (M11 * r1 + nM21 * r0) * invdet;
        Tin_n = fminf(fmaxf(Tin_n, 5.0f), 45.0f);
        Te = Te_n; Tin = Tin_n;
        out[t] = Tin_n;
    }
}

extern "C" void kernel_launch(void* const* d_in, const int* in_sizes, int n_in,
                              void* d_out, int out_size)
{
    const float* pR_ie = (const float*)d_in[0];
    const float* pR_ea = (const float*)d_in[1];
    const float* pC_in = (const float*)d_in[2];
    const float* pC_en = (const float*)d_in[3];
    const float* pA_si = (const float*)d_in[4];
    const float* pA_se = (const float*)d_in[5];
    const float* pA_ii = (const float*)d_in[6];
    const float* pA_ie = (const float*)d_in[7];
    const float* pTin0 = (const float*)d_in[8];
    const float* To   = (const float*)d_in[9];
    const float* Irr  = (const float*)d_in[10];
    const float* Qint = (const float*)d_in[11];
    const float* Qah  = (const float*)d_in[12];
    const float* Ria  = (const float*)d_in[13];
    float* out = (float*)d_out;
    int n = in_sizes[9];

    int C = n / S2;
    if (n > NMAX || n <= 0 || (n % S2) != 0 || (C % TPB) != 0) {
        seq_kernel<<<1, 1>>>(To, Irr, Qint, Qah, Ria,
                             pR_ie, pR_ea, pC_in, pC_en,
                             pA_si, pA_se, pA_ii, pA_ie, pTin0, out, n);
        return;
    }

    static bool attr_set = false;   // idempotent attribute (not a guard on work)
    if (!attr_set) {
        cudaFuncSetAttribute(fused_kernel,
                             cudaFuncAttributeMaxDynamicSharedMemorySize, SMEMB);
        attr_set = true;
    }

    fused_kernel<<<C / TPB, TPB, SMEMB>>>(To, Irr, Qint, Qah, Ria,
                                          pR_ie, pR_ea, pC_in, pC_en,
                                          pA_si, pA_se, pA_ii, pA_ie, pTin0,
                                          out);
}

// round 15
// speedup vs baseline: 1.4252x; 1.4252x over previous
#include <cuda_runtime.h>
#include <cuda_fp16.h>

// RC backward-Euler scan. v11 = v9 with a DEEPER cp.async FIFO.
//  - coefficients 8 B/step: b (fp32) + (h,g) packed __half2, transposed planes
//  - S=128, warm-up = 2 chunks (256 steps), NSEG=3 passes per thread
//  - scan: per-thread cp.async FIFO, DEPTH=16 stages x 4 steps (15 groups =
//    ~975 issue-cycles of prefetch cover > DRAM latency @NAT), dynamic smem
//  - 32-stage segment body fully unrolled (v9); 1 chain/thread, TPB=128

#define DT_S   1800.0f
#define GA     31.388f
#define S2     128
#define PWARM  2
#define NSEG   (PWARM + 1)
#define DEPTH  16
#define TPB    128
#define SMEMB  (DEPTH * TPB * 32)     // 65536 B: float4 b + uint4 hg per stage
#define NMAX   (1 << 22)

static __device__ float4 g_b4[NMAX / 4];    // 4 steps of b per entry
static __device__ uint4  g_hg4[NMAX / 4];   // 4 steps of packed (h,g) per entry

struct DCst {
    float iRie, iRea, invCin, invCen;
    float M11, nM12, nM21;
    float kD, kE, k0a, k1a;
    float gam, del, c_h, c_g1, dtCen;
};

__device__ __forceinline__ DCst make_consts(float R_ie, float R_ea,
                                            float C_in, float C_en)
{
    DCst c;
    c.iRie   = 1.0f / R_ie;
    c.iRea   = 1.0f / R_ea;
    c.invCin = 1.0f / C_in;
    c.invCen = 1.0f / C_en;
    c.M11  = 1.0f + DT_S * (c.iRea + c.iRie) * c.invCen;
    c.nM12 = DT_S * c.iRie * c.invCen;
    c.nM21 = DT_S * c.iRie * c.invCin;
    c.kD   = c.M11  / c.nM12;
    c.kE   = c.nM21 / c.nM12;
    c.k0a  = 1.0f / c.M11;
    c.k1a  = c.nM21 / c.M11;
    float alpha = 1.0f + DT_S * c.iRie * c.invCin;   // M22 = alpha + beta*u
    float beta  = DT_S * c.invCin;
    c.gam  = c.M11 * alpha - c.nM12 * c.nM21;        // det = gam + del*u
    c.del  = c.M11 * beta;
    c.c_h  = c.nM12 * DT_S * c.invCin;
    c.c_g1 = c.M11  * DT_S * c.invCin;
    c.dtCen = DT_S * c.invCen;
    return c;
}

__device__ __forceinline__ float frcp_approx(float x) {
    float r;
    asm("rcp.approx.f32 %0, %1;" : "=f"(r) : "f"(x));
    return r;
}

// ------------------------------------------- pre-pass: compute + transpose
__global__ void __launch_bounds__(256)
pre_t_kernel(const float* __restrict__ To,  const float* __restrict__ Irr,
             const float* __restrict__ Qint, const float* __restrict__ Qah,
             const float* __restrict__ Ria,
             const float* pR_ie, const float* pR_ea,
             const float* pC_in, const float* pC_en,
             const float* pA_si, const float* pA_se,
             const float* pA_ii, const float* pA_ie,
             int C)
{
    __shared__ float4 tb[8][33];
    __shared__ uint4  th[8][33];

    const DCst c = make_consts(__ldg(pR_ie), __ldg(pR_ea), __ldg(pC_in), __ldg(pC_en));
    float a_si = __ldg(pA_si), a_se = __ldg(pA_se);
    float a_ii = __ldg(pA_ii), a_ie = __ldg(pA_ie);

    int j0 = blockIdx.x * 32;
    int k0 = blockIdx.y * 32;

    {   // phase 1: coalesced read + compute
        int kg = threadIdx.x & 7;        // 0..7 (x4 steps)
        int jj = threadIdx.x >> 3;       // 0..31
        int t  = (j0 + jj) * S2 + k0 + 4 * kg;

        float4 to4 = *(const float4*)(To  + t);
        float4 ir4 = *(const float4*)(Irr + t);
        float4 qi4 = *(const float4*)(Qint + t);
        float4 qa4 = *(const float4*)(Qah + t);
        float4 ra4 = *(const float4*)(Ria + t);
        const float* to = (const float*)&to4;
        const float* ir = (const float*)&ir4;
        const float* qi = (const float*)&qi4;
        const float* qa = (const float*)&qa4;
        const float* ra = (const float*)&ra4;

        float Rc[4], P[4], ipv[4];
        #pragma unroll
        for (int i = 0; i < 4; ++i) {
            Rc[i] = fmaxf(ra[i], 1e-4f);
            P[i]  = fmaf(c.gam, Rc[i], c.del);
        }
        float p01 = P[0] * P[1], p23 = P[2] * P[3];
        float ipa = frcp_approx(p01 * p23);
        float i01 = ipa * p23, i23 = ipa * p01;
        ipv[0] = i01 * P[1]; ipv[1] = i01 * P[0];
        ipv[2] = i23 * P[3]; ipv[3] = i23 * P[2];
        #pragma unroll
        for (int i = 0; i < 4; ++i)      // one Newton polish
            ipv[i] = ipv[i] * fmaf(-P[i], ipv[i], 2.0f);

        float4 b4;  float* bp = (float*)&b4;
        uint4  hg4; unsigned* hp = (unsigned*)&hg4;
        #pragma unroll
        for (int i = 0; i < 4; ++i) {
            float ip  = ipv[i];
            float rp  = Rc[i] * ip;                 // invdet
            float Qs  = GA * fminf(fmaxf(ir[i], 0.0f), 2000.0f);
            float qh  = fmaxf(qa[i], 0.0f);
            float b   = c.nM12 * rp;
            float a   = fmaf(c.k1a, b, c.k0a);
            float s0  = c.dtCen * fmaf(to[i], c.iRea,
                                 fmaf(a_se, Qs, a_ie * qi[i]));
            float s1  = fmaf(a_si, Qs, fmaf(a_ii, qi[i], qh));
            float T1  = ip * fmaf(Rc[i], s1, to[i]);
            float h   = fmaf(c.c_h, T1, a * s0);
            float g   = fmaf(c.c_g1, T1, c.nM21 * (rp * s0));
            bp[i] = b;
            __half2 p = __floats2half2_rn(h, g);
            hp[i] = *reinterpret_cast<unsigned*>(&p);
        }
        tb[kg][jj] = b4;
        th[kg][jj] = hg4;
    }
    __syncthreads();
    {   // phase 2: transposed coalesced 512B writes
        int jj = threadIdx.x & 31;
        int kg = threadIdx.x >> 5;       // 0..7
        int idx = ((k0 >> 2) + kg) * C + j0 + jj;
        g_b4[idx]  = tb[kg][jj];
        g_hg4[idx] = th[kg][jj];
    }
}

// ------------------------------------------------------------- scan kernel
__device__ __forceinline__ void cpa16(unsigned saddr, const void* gaddr) {
    asm volatile("cp.async.cg.shared.global [%0], [%1], 16;"
                 :: "r"(saddr), "l"(gaddr));
}
#define CP_COMMIT() asm volatile("cp.async.commit_group;")
#define CP_WAIT()   asm volatile("cp.async.wait_group %0;" :: "n"(DEPTH - 1))

__global__ void __launch_bounds__(TPB)
scan_t_kernel(float* __restrict__ out,
              const float* pR_ie, const float* pR_ea,
              const float* pC_in, const float* pC_en,
              const float* pTin0, int C)
{
    extern __shared__ char dyn[];
    float4* sb = (float4*)dyn;                       // [DEPTH][TPB]
    uint4*  sh = (uint4*)(dyn + DEPTH * TPB * 16);   // [DEPTH][TPB]

    int tid = threadIdx.x;
    int j = blockIdx.x * TPB + tid;

    const DCst c = make_consts(__ldg(pR_ie), __ldg(pR_ea), __ldg(pC_in), __ldg(pC_en));
    float kD = c.kD, kE = c.kE, k0a = c.k0a, k1a = c.k1a;
    float Tin0 = __ldg(pTin0);

    unsigned sb_base = (unsigned)__cvta_generic_to_shared(sb + tid);
    unsigned sh_base = (unsigned)__cvta_generic_to_shared(sh + tid);
    int colBase = j - PWARM;

    // prologue: stages 0..DEPTH-2 (all within segment 0: DEPTH-1 = 15 < 32)
    {
        int col0 = colBase < 0 ? 0 : colBase;
        const float4* pb = g_b4  + col0;
        const uint4*  ph = g_hg4 + col0;
        #pragma unroll
        for (int s = 0; s < DEPTH - 1; ++s) {
            cpa16(sb_base + (unsigned)(s & (DEPTH - 1)) * (TPB * 16), pb + (size_t)s * C);
            cpa16(sh_base + (unsigned)(s & (DEPTH - 1)) * (TPB * 16), ph + (size_t)s * C);
            CP_COMMIT();
        }
    }

    float Te = Tin0, Tin = Tin0;
    float* outBase = out + j * S2;

    #pragma unroll 1
    for (int seg = 0; seg < NSEG; ++seg) {
        int colC = colBase + seg;     if (colC < 0) colC = 0;
        int cn   = colBase + seg + 1;
        int colN = cn < 0 ? 0 : (cn > C - 1 ? C - 1 : cn);
        bool doOut = (seg == PWARM);

        const float4* pbC = g_b4  + colC;
        const uint4*  phC = g_hg4 + colC;
        const float4* pbN = g_b4  + colN;
        const uint4*  phN = g_hg4 + colN;

        #pragma unroll
        for (int m = 0; m < 32; ++m) {
            // prefetch stage m+DEPTH-1 (static column/row selection)
            {
                const int pr = m + DEPTH - 1;
                if (pr < 32) {
                    cpa16(sb_base + (unsigned)(pr & (DEPTH - 1)) * (TPB * 16), pbC + (size_t)pr * C);
                    cpa16(sh_base + (unsigned)(pr & (DEPTH - 1)) * (TPB * 16), phC + (size_t)pr * C);
                } else {
                    const int r = pr - 32;
                    cpa16(sb_base + (unsigned)(pr & (DEPTH - 1)) * (TPB * 16), pbN + (size_t)r * C);
                    cpa16(sh_base + (unsigned)(pr & (DEPTH - 1)) * (TPB * 16), phN + (size_t)r * C);
                }
            }
            CP_COMMIT();
            CP_WAIT();

            float4 b4  = sb[(m & (DEPTH - 1)) * TPB + tid];
            uint4  hg4 = sh[(m & (DEPTH - 1)) * TPB + tid];
            const float*    bb = (const float*)&b4;
            const unsigned* hh = (const unsigned*)&hg4;

            float4 v; float* vv = (float*)&v;
            #pragma unroll
            for (int e = 0; e < 4; ++e) {
                float b = bb[e];
                unsigned u = hh[e];
                float2 hg = __half22float2(*reinterpret_cast<const __half2*>(&u));
                float a  = fmaf(k1a, b, k0a);
                float dd = kD * b;
                float ee = kE * b;
                float p  = fmaf(b,  Tin, hg.x);
                float q  = fmaf(ee, Te,  hg.y);
                float Te_n  = fmaf(a,  Te,  p);
                float Tin_n = fmaf(dd, Tin, q);
                Tin_n = fminf(fmaxf(Tin_n, 5.0f), 45.0f);
                Te = Te_n; Tin = Tin_n;
                vv[e] = Tin;
            }
            if (doOut) __stcs((float4*)(outBase + m * 4), v);
        }

        // segment used a clamped (dummy) column: restore exact initial carry
        if (colBase + seg < 0) { Te = Tin0; Tin = Tin0; }
    }
}

// ------------------------------------------- exact fallback (ragged n only)
__global__ void seq_kernel(const float* __restrict__ To, const float* __restrict__ Irr,
                           const float* __restrict__ Qint, const float* __restrict__ Qah,
                           const float* __restrict__ Ria,
                           const float* pR_ie, const float* pR_ea,
                           const float* pC_in, const float* pC_en,
                           const float* pA_si, const float* pA_se,
                           const float* pA_ii, const float* pA_ie,
                           const float* pTin0,
                           float* __restrict__ out, int n)
{
    float iRie = 1.0f / *pR_ie, iRea = 1.0f / *pR_ea;
    float invCin = 1.0f / *pC_in, invCen = 1.0f / *pC_en;
    float a_si = *pA_si, a_se = *pA_se, a_ii = *pA_ii, a_ie = *pA_ie;
    float M11  = 1.0f + DT_S * (iRea + iRie) * invCen;
    float nM12 = DT_S * iRie * invCen;
    float nM21 = DT_S * iRie * invCin;
    float Te = *pTin0, Tin = *pTin0;
    for (int t = 0; t < n; ++t) {
        float Ria_c = fmaxf(Ria[t], 1e-4f);
        float u     = 1.0f / Ria_c;
        float Qsol  = GA * fminf(fmaxf(Irr[t], 0.0f), 2000.0f);
        float qah   = fmaxf(Qah[t], 0.0f);
        float M22 = 1.0f + DT_S * (u + iRie) * invCin;
        float det = M11 * M22 - nM12 * nM21;
        float invdet = 1.0f / det;
        float b0 = To[t] * iRea * invCen + (a_se * Qsol + a_ie * Qint[t]) * invCen;
        float b1 = (To[t] * u + a_si * Qsol + a_ii * Qint[t] + qah) * invCin;
        float r0 = Te + DT_S * b0;
        float r1 = Tin + DT_S * b1;
        float Te_n  = (M22 * r0 + nM12 * r1) * invdet;
        float Tin_n = (M11 * r1 + nM21 * r0) * invdet;
        Tin_n = fminf(fmaxf(Tin_n, 5.0f), 45.0f);
        Te = Te_n; Tin = Tin_n;
        out[t] = Tin_n;
    }
}

extern "C" void kernel_launch(void* const* d_in, const int* in_sizes, int n_in,
                              void* d_out, int out_size)
{
    const float* pR_ie = (const float*)d_in[0];
    const float* pR_ea = (const float*)d_in[1];
    const float* pC_in = (const float*)d_in[2];
    const float* pC_en = (const float*)d_in[3];
    const float* pA_si = (const float*)d_in[4];
    const float* pA_se = (const float*)d_in[5];
    const float* pA_ii = (const float*)d_in[6];
    const float* pA_ie = (const float*)d_in[7];
    const float* pTin0 = (const float*)d_in[8];
    const float* To   = (const float*)d_in[9];
    const float* Irr  = (const float*)d_in[10];
    const float* Qint = (const float*)d_in[11];
    const float* Qah  = (const float*)d_in[12];
    const float* Ria  = (const float*)d_in[13];
    float* out = (float*)d_out;
    int n = in_sizes[9];

    int C = n / S2;
    if (n > NMAX || n <= 0 || (n % S2) != 0 || (C % TPB) != 0) {
        seq_kernel<<<1, 1>>>(To, Irr, Qint, Qah, Ria,
                             pR_ie, pR_ea, pC_in, pC_en,
                             pA_si, pA_se, pA_ii, pA_ie, pTin0, out, n);
        return;
    }

    static bool attr_set = false;   // idempotent attribute (not a work guard)
    if (!attr_set) {
        cudaFuncSetAttribute(scan_t_kernel,
                             cudaFuncAttributeMaxDynamicSharedMemorySize, SMEMB);
        attr_set = true;
    }

    dim3 pgrid(C / 32, S2 / 32);             // (1024, 4) blocks of 256
    pre_t_kernel<<<pgrid, 256>>>(To, Irr, Qint, Qah, Ria,
                                 pR_ie, pR_ea, pC_in, pC_en,
                                 pA_si, pA_se, pA_ii, pA_ie, C);

    scan_t_kernel<<<C / TPB, TPB, SMEMB>>>(out, pR_ie, pR_ea, pC_in, pC_en,
                                           pTin0, C);
}

// round 17
// speedup vs baseline: 1.4988x; 1.0517x over previous
#include <cuda_runtime.h>
#include <cuda_fp16.h>

// RC backward-Euler scan. v12 = v11 with PWARM=1 (redundancy 3x -> 2x).
//  - scan is L2-bandwidth-bound at ~50% LTS cap: cut bytes, cut time.
//  - coefficients 8 B/step: b (fp32) + (h,g) packed __half2, transposed planes
//  - S=128, warm-up = 1 chunk (128 steps; lambda~0.02/step -> ~6e-5 rel err)
//  - scan: per-thread cp.async FIFO DEPTH=16, 32-stage body fully unrolled

#define DT_S   1800.0f
#define GA     31.388f
#define S2     128
#define PWARM  1
#define NSEG   (PWARM + 1)
#define DEPTH  16
#define TPB    128
#define SMEMB  (DEPTH * TPB * 32)     // 65536 B: float4 b + uint4 hg per stage
#define NMAX   (1 << 22)

static __device__ float4 g_b4[NMAX / 4];    // 4 steps of b per entry
static __device__ uint4  g_hg4[NMAX / 4];   // 4 steps of packed (h,g) per entry

struct DCst {
    float iRie, iRea, invCin, invCen;
    float M11, nM12, nM21;
    float kD, kE, k0a, k1a;
    float gam, del, c_h, c_g1, dtCen;
};

__device__ __forceinline__ DCst make_consts(float R_ie, float R_ea,
                                            float C_in, float C_en)
{
    DCst c;
    c.iRie   = 1.0f / R_ie;
    c.iRea   = 1.0f / R_ea;
    c.invCin = 1.0f / C_in;
    c.invCen = 1.0f / C_en;
    c.M11  = 1.0f + DT_S * (c.iRea + c.iRie) * c.invCen;
    c.nM12 = DT_S * c.iRie * c.invCen;
    c.nM21 = DT_S * c.iRie * c.invCin;
    c.kD   = c.M11  / c.nM12;
    c.kE   = c.nM21 / c.nM12;
    c.k0a  = 1.0f / c.M11;
    c.k1a  = c.nM21 / c.M11;
    float alpha = 1.0f + DT_S * c.iRie * c.invCin;   // M22 = alpha + beta*u
    float beta  = DT_S * c.invCin;
    c.gam  = c.M11 * alpha - c.nM12 * c.nM21;        // det = gam + del*u
    c.del  = c.M11 * beta;
    c.c_h  = c.nM12 * DT_S * c.invCin;
    c.c_g1 = c.M11  * DT_S * c.invCin;
    c.dtCen = DT_S * c.invCen;
    return c;
}

__device__ __forceinline__ float frcp_approx(float x) {
    float r;
    asm("rcp.approx.f32 %0, %1;" : "=f"(r) : "f"(x));
    return r;
}

// ------------------------------------------- pre-pass: compute + transpose
__global__ void __launch_bounds__(256)
pre_t_kernel(const float* __restrict__ To,  const float* __restrict__ Irr,
             const float* __restrict__ Qint, const float* __restrict__ Qah,
             const float* __restrict__ Ria,
             const float* pR_ie, const float* pR_ea,
             const float* pC_in, const float* pC_en,
             const float* pA_si, const float* pA_se,
             const float* pA_ii, const float* pA_ie,
             int C)
{
    __shared__ float4 tb[8][33];
    __shared__ uint4  th[8][33];

    const DCst c = make_consts(__ldg(pR_ie), __ldg(pR_ea), __ldg(pC_in), __ldg(pC_en));
    float a_si = __ldg(pA_si), a_se = __ldg(pA_se);
    float a_ii = __ldg(pA_ii), a_ie = __ldg(pA_ie);

    int j0 = blockIdx.x * 32;
    int k0 = blockIdx.y * 32;

    {   // phase 1: coalesced read + compute
        int kg = threadIdx.x & 7;        // 0..7 (x4 steps)
        int jj = threadIdx.x >> 3;       // 0..31
        int t  = (j0 + jj) * S2 + k0 + 4 * kg;

        float4 to4 = *(const float4*)(To  + t);
        float4 ir4 = *(const float4*)(Irr + t);
        float4 qi4 = *(const float4*)(Qint + t);
        float4 qa4 = *(const float4*)(Qah + t);
        float4 ra4 = *(const float4*)(Ria + t);
        const float* to = (const float*)&to4;
        const float* ir = (const float*)&ir4;
        const float* qi = (const float*)&qi4;
        const float* qa = (const float*)&qa4;
        const float* ra = (const float*)&ra4;

        float Rc[4], P[4], ipv[4];
        #pragma unroll
        for (int i = 0; i < 4; ++i) {
            Rc[i] = fmaxf(ra[i], 1e-4f);
            P[i]  = fmaf(c.gam, Rc[i], c.del);
        }
        float p01 = P[0] * P[1], p23 = P[2] * P[3];
        float ipa = frcp_approx(p01 * p23);
        float i01 = ipa * p23, i23 = ipa * p01;
        ipv[0] = i01 * P[1]; ipv[1] = i01 * P[0];
        ipv[2] = i23 * P[3]; ipv[3] = i23 * P[2];
        #pragma unroll
        for (int i = 0; i < 4; ++i)      // one Newton polish
            ipv[i] = ipv[i] * fmaf(-P[i], ipv[i], 2.0f);

        float4 b4;  float* bp = (float*)&b4;
        uint4  hg4; unsigned* hp = (unsigned*)&hg4;
        #pragma unroll
        for (int i = 0; i < 4; ++i) {
            float ip  = ipv[i];
            float rp  = Rc[i] * ip;                 // invdet
            float Qs  = GA * fminf(fmaxf(ir[i], 0.0f), 2000.0f);
            float qh  = fmaxf(qa[i], 0.0f);
            float b   = c.nM12 * rp;
            float a   = fmaf(c.k1a, b, c.k0a);
            float s0  = c.dtCen * fmaf(to[i], c.iRea,
                                 fmaf(a_se, Qs, a_ie * qi[i]));
            float s1  = fmaf(a_si, Qs, fmaf(a_ii, qi[i], qh));
            float T1  = ip * fmaf(Rc[i], s1, to[i]);
            float h   = fmaf(c.c_h, T1, a * s0);
            float g   = fmaf(c.c_g1, T1, c.nM21 * (rp * s0));
            bp[i] = b;
            __half2 p = __floats2half2_rn(h, g);
            hp[i] = *reinterpret_cast<unsigned*>(&p);
        }
        tb[kg][jj] = b4;
        th[kg][jj] = hg4;
    }
    __syncthreads();
    {   // phase 2: transposed coalesced 512B writes
        int jj = threadIdx.x & 31;
        int kg = threadIdx.x >> 5;       // 0..7
        int idx = ((k0 >> 2) + kg) * C + j0 + jj;
        g_b4[idx]  = tb[kg][jj];
        g_hg4[idx] = th[kg][jj];
    }
}

// ------------------------------------------------------------- scan kernel
__device__ __forceinline__ void cpa16(unsigned saddr, const void* gaddr) {
    asm volatile("cp.async.cg.shared.global [%0], [%1], 16;"
                 :: "r"(saddr), "l"(gaddr));
}
#define CP_COMMIT() asm volatile("cp.async.commit_group;")
#define CP_WAIT()   asm volatile("cp.async.wait_group %0;" :: "n"(DEPTH - 1))

__global__ void __launch_bounds__(TPB)
scan_t_kernel(float* __restrict__ out,
              const float* pR_ie, const float* pR_ea,
              const float* pC_in, const float* pC_en,
              const float* pTin0, int C)
{
    extern __shared__ char dyn[];
    float4* sb = (float4*)dyn;                       // [DEPTH][TPB]
    uint4*  sh = (uint4*)(dyn + DEPTH * TPB * 16);   // [DEPTH][TPB]

    int tid = threadIdx.x;
    int j = blockIdx.x * TPB + tid;

    const DCst c = make_consts(__ldg(pR_ie), __ldg(pR_ea), __ldg(pC_in), __ldg(pC_en));
    float kD = c.kD, kE = c.kE, k0a = c.k0a, k1a = c.k1a;
    float Tin0 = __ldg(pTin0);

    unsigned sb_base = (unsigned)__cvta_generic_to_shared(sb + tid);
    unsigned sh_base = (unsigned)__cvta_generic_to_shared(sh + tid);
    int colBase = j - PWARM;

    // prologue: stages 0..DEPTH-2 (all within segment 0: DEPTH-1 = 15 < 32)
    {
        int col0 = colBase < 0 ? 0 : colBase;
        const float4* pb = g_b4  + col0;
        const uint4*  ph = g_hg4 + col0;
        #pragma unroll
        for (int s = 0; s < DEPTH - 1; ++s) {
            cpa16(sb_base + (unsigned)(s & (DEPTH - 1)) * (TPB * 16), pb + (size_t)s * C);
            cpa16(sh_base + (unsigned)(s & (DEPTH - 1)) * (TPB * 16), ph + (size_t)s * C);
            CP_COMMIT();
        }
    }

    float Te = Tin0, Tin = Tin0;
    float* outBase = out + j * S2;

    #pragma unroll 1
    for (int seg = 0; seg < NSEG; ++seg) {
        int colC = colBase + seg;     if (colC < 0) colC = 0;
        int cn   = colBase + seg + 1;
        int colN = cn < 0 ? 0 : (cn > C - 1 ? C - 1 : cn);
        bool doOut = (seg == PWARM);

        const float4* pbC = g_b4  + colC;
        const uint4*  phC = g_hg4 + colC;
        const float4* pbN = g_b4  + colN;
        const uint4*  phN = g_hg4 + colN;

        #pragma unroll
        for (int m = 0; m < 32; ++m) {
            // prefetch stage m+DEPTH-1 (static column/row selection)
            {
                const int pr = m + DEPTH - 1;
                if (pr < 32) {
                    cpa16(sb_base + (unsigned)(pr & (DEPTH - 1)) * (TPB * 16), pbC + (size_t)pr * C);
                    cpa16(sh_base + (unsigned)(pr & (DEPTH - 1)) * (TPB * 16), phC + (size_t)pr * C);
                } else {
                    const int r = pr - 32;
                    cpa16(sb_base + (unsigned)(pr & (DEPTH - 1)) * (TPB * 16), pbN + (size_t)r * C);
                    cpa16(sh_base + (unsigned)(pr & (DEPTH - 1)) * (TPB * 16), phN + (size_t)r * C);
                }
            }
            CP_COMMIT();
            CP_WAIT();

            float4 b4  = sb[(m & (DEPTH - 1)) * TPB + tid];
            uint4  hg4 = sh[(m & (DEPTH - 1)) * TPB + tid];
            const float*    bb = (const float*)&b4;
            const unsigned* hh = (const unsigned*)&hg4;

            float4 v; float* vv = (float*)&v;
            #pragma unroll
            for (int e = 0; e < 4; ++e) {
                float b = bb[e];
                unsigned u = hh[e];
                float2 hg = __half22float2(*reinterpret_cast<const __half2*>(&u));
                float a  = fmaf(k1a, b, k0a);
                float dd = kD * b;
                float ee = kE * b;
                float p  = fmaf(b,  Tin, hg.x);
                float q  = fmaf(ee, Te,  hg.y);
                float Te_n  = fmaf(a,  Te,  p);
                float Tin_n = fmaf(dd, Tin, q);
                Tin_n = fminf(fmaxf(Tin_n, 5.0f), 45.0f);
                Te = Te_n; Tin = Tin_n;
                vv[e] = Tin;
            }
            if (doOut) __stcs((float4*)(outBase + m * 4), v);
        }

        // segment used a clamped (dummy) column: restore exact initial carry
        if (colBase + seg < 0) { Te = Tin0; Tin = Tin0; }
    }
}

// ------------------------------------------- exact fallback (ragged n only)
__global__ void seq_kernel(const float* __restrict__ To, const float* __restrict__ Irr,
                           const float* __restrict__ Qint, const float* __restrict__ Qah,
                           const float* __restrict__ Ria,
                           const float* pR_ie, const float* pR_ea,
                           const float* pC_in, const float* pC_en,
                           const float* pA_si, const float* pA_se,
                           const float* pA_ii, const float* pA_ie,
                           const float* pTin0,
                           float* __restrict__ out, int n)
{
    float iRie = 1.0f / *pR_ie, iRea = 1.0f / *pR_ea;
    float invCin = 1.0f / *pC_in, invCen = 1.0f / *pC_en;
    float a_si = *pA_si, a_se = *pA_se, a_ii = *pA_ii, a_ie = *pA_ie;
    float M11  = 1.0f + DT_S * (iRea + iRie) * invCen;
    float nM12 = DT_S * iRie * invCen;
    float nM21 = DT_S * iRie * invCin;
    float Te = *pTin0, Tin = *pTin0;
    for (int t = 0; t < n; ++t) {
        float Ria_c = fmaxf(Ria[t], 1e-4f);
        float u     = 1.0f / Ria_c;
        float Qsol  = GA * fminf(fmaxf(Irr[t], 0.0f), 2000.0f);
        float qah   = fmaxf(Qah[t], 0.0f);
        float M22 = 1.0f + DT_S * (u + iRie) * invCin;
        float det = M11 * M22 - nM12 * nM21;
        float invdet = 1.0f / det;
        float b0 = To[t] * iRea * invCen + (a_se * Qsol + a_ie * Qint[t]) * invCen;
        float b1 = (To[t] * u + a_si * Qsol + a_ii * Qint[t] + qah) * invCin;
        float r0 = Te + DT_S * b0;
        float r1 = Tin + DT_S * b1;
        float Te_n  = (M22 * r0 + nM12 * r1) * invdet;
        float Tin_n = (M11 * r1 + nM21 * r0) * invdet;
        Tin_n = fminf(fmaxf(Tin_n, 5.0f), 45.0f);
        Te = Te_n; Tin = Tin_n;
        out[t] = Tin_n;
    }
}

extern "C" void kernel_launch(void* const* d_in, const int* in_sizes, int n_in,
                              void* d_out, int out_size)
{
    const float* pR_ie = (const float*)d_in[0];
    const float* pR_ea = (const float*)d_in[1];
    const float* pC_in = (const float*)d_in[2];
    const float* pC_en = (const float*)d_in[3];
    const float* pA_si = (const float*)d_in[4];
    const float* pA_se = (const float*)d_in[5];
    const float* pA_ii = (const float*)d_in[6];
    const float* pA_ie = (const float*)d_in[7];
    const float* pTin0 = (const float*)d_in[8];
    const float* To   = (const float*)d_in[9];
    const float* Irr  = (const float*)d_in[10];
    const float* Qint = (const float*)d_in[11];
    const float* Qah  = (const float*)d_in[12];
    const float* Ria  = (const float*)d_in[13];
    float* out = (float*)d_out;
    int n = in_sizes[9];

    int C = n / S2;
    if (n > NMAX || n <= 0 || (n % S2) != 0 || (C % TPB) != 0) {
        seq_kernel<<<1, 1>>>(To, Irr, Qint, Qah, Ria,
                             pR_ie, pR_ea, pC_in, pC_en,
                             pA_si, pA_se, pA_ii, pA_ie, pTin0, out, n);
        return;
    }

    static bool attr_set = false;   // idempotent attribute (not a work guard)
    if (!attr_set) {
        cudaFuncSetAttribute(scan_t_kernel,
                             cudaFuncAttributeMaxDynamicSharedMemorySize, SMEMB);
        attr_set = true;
    }

    dim3 pgrid(C / 32, S2 / 32);             // (1024, 4) blocks of 256
    pre_t_kernel<<<pgrid, 256>>>(To, Irr, Qint, Qah, Ria,
                                 pR_ie, pR_ea, pC_in, pC_en,
                                 pA_si, pA_se, pA_ii, pA_ie, C);

    scan_t_kernel<<<C / TPB, TPB, SMEMB>>>(out, pR_ie, pR_ea, pC_in, pC_en,
                                           pTin0, C);
}